// round 2
// baseline (speedup 1.0000x reference)
#include <cuda_runtime.h>
#include <cstdint>
#include <cstddef>

// Problem shape (fixed by dataset)
#define NN   8192
#define IC   128
#define OC   16
#define KH   3
#define MT   1024            // m-tile size (support rows cached in smem per tile)
#define PLANE 1088           // ull elements per d-pair plane (>= MT + MT/16)
#define SMEM_BYTES (8 * PLANE * 8)   // 8 planes of PLANE ull = 69632 B

typedef unsigned long long ull;

// Scratch: support = x@w + b, fp32 [NN][OC]. 512 KB, L2-resident.
__device__ __align__(16) float g_support[NN * OC];

// ---------- packed f32x2 helpers ----------
__device__ __forceinline__ ull pack_dup(float v) {
    ull r; asm("mov.b64 %0, {%1, %1};" : "=l"(r) : "f"(v)); return r;
}
__device__ __forceinline__ ull pack2(float x, float y) {
    ull r; asm("mov.b64 %0, {%1, %2};" : "=l"(r) : "f"(x), "f"(y)); return r;
}
__device__ __forceinline__ void ffma2(ull& d, ull a, ull b) {
    asm("fma.rn.f32x2 %0, %1, %2, %0;" : "+l"(d) : "l"(a), "l"(b));
}
__device__ __forceinline__ ull addf2(ull a, ull b) {
    ull r; asm("add.rn.f32x2 %0, %1, %2;" : "=l"(r) : "l"(a), "l"(b)); return r;
}

// ---------- kernel 1: support[m][d] = sum_c x[m][c]*w[c][d] + b[d] ----------
__global__ void __launch_bounds__(128)
support_kernel(const float* __restrict__ x, const float* __restrict__ w,
               const float* __restrict__ b) {
    __shared__ ull wsm[IC * OC / 2];   // w packed into f32x2 pairs: [c][j], j=d/2
    __shared__ ull bsm[OC / 2];
    int tid = threadIdx.x;
    for (int i = tid; i < IC * OC / 2; i += 128) wsm[i] = ((const ull*)w)[i];
    if (tid < OC / 2) bsm[tid] = ((const ull*)b)[tid];
    __syncthreads();

    int m = blockIdx.x * 128 + tid;   // one row per thread
    ull acc[8];
#pragma unroll
    for (int j = 0; j < 8; j++) acc[j] = bsm[j];

    const float4* xr = (const float4*)(x + (size_t)m * IC);
#pragma unroll 4
    for (int c4 = 0; c4 < IC / 4; c4++) {
        float4 xv = xr[c4];
#pragma unroll
        for (int e = 0; e < 4; e++) {
            float xs = (&xv.x)[e];
            ull a2 = pack_dup(xs);
            int c = c4 * 4 + e;
#pragma unroll
            for (int j = 0; j < 8; j++) ffma2(acc[j], a2, wsm[c * 8 + j]);
        }
    }
    ull* o = (ull*)g_support;
#pragma unroll
    for (int j = 0; j < 8; j++) o[(size_t)m * 8 + j] = acc[j];
}

// ---------- kernel 2: out[n][d] = sum_k att_k * sum_m adj[k][n][m]*support[m][d] ----------
// Thread map: 128 threads/CTA. tid = r2*8 + s. Each thread owns rows
// (blk*32 + r2) and (blk*32 + r2 + 16); slot s takes float4 chunks fl%8 == s.
// Support tile lives in smem as 8 f32x2 "planes" (one per output-col pair).
// INJECTIVE pad: idx = m + (m>>4)  (+1 ull per 16 elems). Reader lanes s=0..7
// hit ull indices 4s+(s>>2)+34i -> bank pairs {0,8,16,24,2,10,18,26}: conflict-free.
__global__ void __launch_bounds__(128, 2)
gcn_main(const float* __restrict__ adj, const float* __restrict__ attp,
         float* __restrict__ out) {
    extern __shared__ ull sp[];
    int tid = threadIdx.x;
    int s   = tid & 7;
    int r2  = tid >> 3;                 // 0..15
    int rowA = blockIdx.x * 32 + r2;
    int rowB = rowA + 16;

    // softmax over the 3 hop attention params (all threads compute; trivial)
    float p0 = attp[0], p1 = attp[1], p2 = attp[2];
    float mx = fmaxf(p0, fmaxf(p1, p2));
    float e0 = expf(p0 - mx), e1 = expf(p1 - mx), e2 = expf(p2 - mx);
    float inv = 1.0f / (e0 + e1 + e2);
    float att[KH] = {e0 * inv, e1 * inv, e2 * inv};

    ull acc[16];                         // [0..7] rowA pairs, [8..15] rowB pairs
#pragma unroll
    for (int j = 0; j < 16; j++) acc[j] = 0ull;

    const float4* supp4 = (const float4*)g_support;

    for (int k = 0; k < KH; k++) {
        const float4* pAr = (const float4*)(adj + ((size_t)k * NN + rowA) * NN);
        const float4* pBr = (const float4*)(adj + ((size_t)k * NN + rowB) * NN);
        float ak = att[k];

        for (int t = 0; t < NN / MT; t++) {
            int tile0 = t * MT;
            __syncthreads();   // protect previous tile's readers
            // cooperative load of support tile (att_k folded in)
            for (int idx = tid; idx < MT * (OC / 4); idx += 128) {
                int m  = idx >> 2;
                int dq = idx & 3;
                float4 v = supp4[(size_t)(tile0 + m) * (OC / 4) + dq];
                int base = m + (m >> 4);          // injective pad
                int j0 = dq * 2;
                sp[(size_t)j0 * PLANE + base]       = pack2(v.x * ak, v.y * ak);
                sp[(size_t)(j0 + 1) * PLANE + base] = pack2(v.z * ak, v.w * ak);
            }
            __syncthreads();

            const float4* pA = pAr + (tile0 >> 2);
            const float4* pB = pBr + (tile0 >> 2);

            // software-pipelined stream over 256 float4s of this tile
            float4 c0a = pA[s],     c0b = pB[s];
            float4 c1a = pA[s + 8], c1b = pB[s + 8];
#pragma unroll 1
            for (int i = 0; i < 32; i += 2) {
                int f2i = s + 8 * (i + 2); if (f2i > 255) f2i = s;
                int f3i = s + 8 * (i + 3); if (f3i > 255) f3i = s;
                float4 n0a = pA[f2i], n0b = pB[f2i];
                float4 n1a = pA[f3i], n1b = pB[f3i];
                {
                    int fl = s + 8 * i;
                    int base = 4 * fl + (fl >> 2);   // matches m + (m>>4), m=4fl..4fl+3
#pragma unroll
                    for (int jp = 0; jp < 4; jp++) {
                        ull va = pack_dup((&c0a.x)[jp]);
                        ull vb = pack_dup((&c0b.x)[jp]);
                        const ull* q = sp + base + jp;
#pragma unroll
                        for (int j = 0; j < 8; j++) {
                            ull sv = q[(size_t)j * PLANE];
                            ffma2(acc[j],     va, sv);
                            ffma2(acc[8 + j], vb, sv);
                        }
                    }
                }
                {
                    int fl = s + 8 * i + 8;
                    int base = 4 * fl + (fl >> 2);
#pragma unroll
                    for (int jp = 0; jp < 4; jp++) {
                        ull va = pack_dup((&c1a.x)[jp]);
                        ull vb = pack_dup((&c1b.x)[jp]);
                        const ull* q = sp + base + jp;
#pragma unroll
                        for (int j = 0; j < 8; j++) {
                            ull sv = q[(size_t)j * PLANE];
                            ffma2(acc[j],     va, sv);
                            ffma2(acc[8 + j], vb, sv);
                        }
                    }
                }
                c0a = n0a; c0b = n0b; c1a = n1a; c1b = n1b;
            }
        }
    }

    // reduce the 8 m-slots of each row (lanes s=0..7 within the same warp)
#pragma unroll
    for (int j = 0; j < 16; j++) {
        acc[j] = addf2(acc[j], __shfl_xor_sync(0xffffffffu, acc[j], 4));
        acc[j] = addf2(acc[j], __shfl_xor_sync(0xffffffffu, acc[j], 2));
        acc[j] = addf2(acc[j], __shfl_xor_sync(0xffffffffu, acc[j], 1));
    }
    if (s == 0) {
        ull* op = (ull*)out;
#pragma unroll
        for (int j = 0; j < 8; j++) {
            op[(size_t)rowA * 8 + j] = acc[j];
            op[(size_t)rowB * 8 + j] = acc[8 + j];
        }
    }
}

extern "C" void kernel_launch(void* const* d_in, const int* in_sizes, int n_in,
                              void* d_out, int out_size) {
    const float* x    = (const float*)d_in[0];
    const float* w    = (const float*)d_in[1];
    const float* b    = (const float*)d_in[2];
    const float* adj  = (const float*)d_in[3];
    const float* attp = (const float*)d_in[4];
    float* out = (float*)d_out;

    support_kernel<<<NN / 128, 128>>>(x, w, b);

    cudaFuncSetAttribute(gcn_main, cudaFuncAttributeMaxDynamicSharedMemorySize,
                         SMEM_BYTES);
    gcn_main<<<NN / 32, 128, SMEM_BYTES>>>(adj, attp, out);
}

// round 3
// speedup vs baseline: 1.3030x; 1.3030x over previous
#include <cuda_runtime.h>
#include <cstdint>
#include <cstddef>

#define NN   8192
#define IC   128
#define OC   16
#define KH   3
#define MT   1024            // m-tile rows cached in smem
#define PLANE 1088           // ull per d-pair plane (>= MT + MT/16)
#define SMEM_BYTES (8 * PLANE * 8)   // 69632 B
#define MSPLIT 4             // m-dimension split across CTAs

typedef unsigned long long ull;

__device__ __align__(16) float g_support[NN * OC];            // 512 KB
__device__ __align__(16) float g_partial[MSPLIT * NN * OC];   // 2 MB

// ---------- packed f32x2 helpers ----------
__device__ __forceinline__ ull pack_dup(float v) {
    ull r; asm("mov.b64 %0, {%1, %1};" : "=l"(r) : "f"(v)); return r;
}
__device__ __forceinline__ ull pack2(float x, float y) {
    ull r; asm("mov.b64 %0, {%1, %2};" : "=l"(r) : "f"(x), "f"(y)); return r;
}
__device__ __forceinline__ void ffma2(ull& d, ull a, ull b) {
    asm("fma.rn.f32x2 %0, %1, %2, %0;" : "+l"(d) : "l"(a), "l"(b));
}
__device__ __forceinline__ ull addf2(ull a, ull b) {
    ull r; asm("add.rn.f32x2 %0, %1, %2;" : "=l"(r) : "l"(a), "l"(b)); return r;
}

// ---------- kernel 1: support = x@w + b ----------
__global__ void __launch_bounds__(128)
support_kernel(const float* __restrict__ x, const float* __restrict__ w,
               const float* __restrict__ b) {
    __shared__ ull wsm[IC * OC / 2];
    __shared__ ull bsm[OC / 2];
    int tid = threadIdx.x;
    for (int i = tid; i < IC * OC / 2; i += 128) wsm[i] = ((const ull*)w)[i];
    if (tid < OC / 2) bsm[tid] = ((const ull*)b)[tid];
    __syncthreads();

    int m = blockIdx.x * 128 + tid;
    ull acc[8];
#pragma unroll
    for (int j = 0; j < 8; j++) acc[j] = bsm[j];

    const float4* xr = (const float4*)(x + (size_t)m * IC);
#pragma unroll 4
    for (int c4 = 0; c4 < IC / 4; c4++) {
        float4 xv = xr[c4];
#pragma unroll
        for (int e = 0; e < 4; e++) {
            ull a2 = pack_dup((&xv.x)[e]);
            int c = c4 * 4 + e;
#pragma unroll
            for (int j = 0; j < 8; j++) ffma2(acc[j], a2, wsm[c * 8 + j]);
        }
    }
    ull* o = (ull*)g_support;
#pragma unroll
    for (int j = 0; j < 8; j++) o[(size_t)m * 8 + j] = acc[j];
}

// ---------- kernel 2: partial[mc][n][d] = sum_k att_k * sum_{m in chunk mc} adj[k][n][m]*support[m][d]
// 128 threads: s = tid&7 (m-slot), r2 = tid>>3 (0..15). Each thread owns 4 rows:
// rb*64 + r2 + 16*r. All 4 rows share every smem support load (4:1 FFMA2:LDS).
// Warp lanes with equal s read identical smem addresses -> 4-way broadcast dedup.
// Injective smem pad: idx = m + (m>>4); PLANE=1088 per d-pair plane.
__global__ void __launch_bounds__(128, 3)
gcn_main(const float* __restrict__ adj, const float* __restrict__ attp) {
    extern __shared__ ull sp[];
    int tid = threadIdx.x;
    int s   = tid & 7;
    int r2  = tid >> 3;                  // 0..15
    int rb  = blockIdx.x;                // row block (64 rows)
    int mc  = blockIdx.y;                // m chunk (2048 m)

    // softmax over hop attention params
    float p0 = attp[0], p1 = attp[1], p2 = attp[2];
    float mx = fmaxf(p0, fmaxf(p1, p2));
    float e0 = expf(p0 - mx), e1 = expf(p1 - mx), e2 = expf(p2 - mx);
    float inv = 1.0f / (e0 + e1 + e2);
    float att[KH] = {e0 * inv, e1 * inv, e2 * inv};

    int row0 = rb * 64 + r2;             // rows: row0 + 16*r, r=0..3

    ull acc[32];                         // acc[r*8+j]
#pragma unroll
    for (int j = 0; j < 32; j++) acc[j] = 0ull;

    const float4* supp4 = (const float4*)g_support;

    for (int k = 0; k < KH; k++) {
        const float4* pr[4];
#pragma unroll
        for (int r = 0; r < 4; r++)
            pr[r] = (const float4*)(adj + ((size_t)k * NN + row0 + 16 * r) * NN);
        float ak = att[k];

        for (int t = 0; t < 2; t++) {
            int tile0 = (mc * 2 + t) * MT;
            __syncthreads();
            // cooperative tile load (att_k folded in)
            for (int idx = tid; idx < MT * (OC / 4); idx += 128) {
                int m  = idx >> 2;
                int dq = idx & 3;
                float4 v = supp4[(size_t)(tile0 + m) * (OC / 4) + dq];
                int base = m + (m >> 4);
                int j0 = dq * 2;
                sp[(size_t)j0 * PLANE + base]       = pack2(v.x * ak, v.y * ak);
                sp[(size_t)(j0 + 1) * PLANE + base] = pack2(v.z * ak, v.w * ak);
            }
            __syncthreads();

            const float4* p[4];
#pragma unroll
            for (int r = 0; r < 4; r++) p[r] = pr[r] + (tile0 >> 2);

            // depth-2 prefetch pipeline over 256 float4s of this tile
            float4 c0[4], c1[4];
#pragma unroll
            for (int r = 0; r < 4; r++) { c0[r] = p[r][s]; c1[r] = p[r][s + 8]; }

#pragma unroll 1
            for (int i = 0; i < 32; i += 2) {
                int fa = s + 8 * (i + 2); if (fa > 255) fa = s;
                int fb = s + 8 * (i + 3); if (fb > 255) fb = s;
                float4 na[4], nb[4];
#pragma unroll
                for (int r = 0; r < 4; r++) { na[r] = p[r][fa]; nb[r] = p[r][fb]; }

                {
                    int fl = s + 8 * i;
                    int base = 4 * fl + (fl >> 2);
#pragma unroll
                    for (int jp = 0; jp < 4; jp++) {
                        ull a0 = pack_dup((&c0[0].x)[jp]);
                        ull a1 = pack_dup((&c0[1].x)[jp]);
                        ull a2 = pack_dup((&c0[2].x)[jp]);
                        ull a3 = pack_dup((&c0[3].x)[jp]);
                        const ull* q = sp + base + jp;
#pragma unroll
                        for (int j = 0; j < 8; j++) {
                            ull sv = q[(size_t)j * PLANE];
                            ffma2(acc[j],      a0, sv);
                            ffma2(acc[8 + j],  a1, sv);
                            ffma2(acc[16 + j], a2, sv);
                            ffma2(acc[24 + j], a3, sv);
                        }
                    }
                }
                {
                    int fl = s + 8 * i + 8;
                    int base = 4 * fl + (fl >> 2);
#pragma unroll
                    for (int jp = 0; jp < 4; jp++) {
                        ull a0 = pack_dup((&c1[0].x)[jp]);
                        ull a1 = pack_dup((&c1[1].x)[jp]);
                        ull a2 = pack_dup((&c1[2].x)[jp]);
                        ull a3 = pack_dup((&c1[3].x)[jp]);
                        const ull* q = sp + base + jp;
#pragma unroll
                        for (int j = 0; j < 8; j++) {
                            ull sv = q[(size_t)j * PLANE];
                            ffma2(acc[j],      a0, sv);
                            ffma2(acc[8 + j],  a1, sv);
                            ffma2(acc[16 + j], a2, sv);
                            ffma2(acc[24 + j], a3, sv);
                        }
                    }
                }
#pragma unroll
                for (int r = 0; r < 4; r++) { c0[r] = na[r]; c1[r] = nb[r]; }
            }
        }
    }

    // reduce the 8 m-slots (lanes s=0..7 within warp; r2 bits untouched by xor<8)
#pragma unroll
    for (int j = 0; j < 32; j++) {
        acc[j] = addf2(acc[j], __shfl_xor_sync(0xffffffffu, acc[j], 4));
        acc[j] = addf2(acc[j], __shfl_xor_sync(0xffffffffu, acc[j], 2));
        acc[j] = addf2(acc[j], __shfl_xor_sync(0xffffffffu, acc[j], 1));
    }
    if (s == 0) {
        ull* gp = (ull*)g_partial;
#pragma unroll
        for (int r = 0; r < 4; r++) {
            size_t row = row0 + 16 * r;
#pragma unroll
            for (int j = 0; j < 8; j++)
                gp[((size_t)mc * NN + row) * 8 + j] = acc[r * 8 + j];
        }
    }
}

// ---------- kernel 3: out = sum over MSPLIT partials ----------
__global__ void __launch_bounds__(256)
reduce_kernel(float* __restrict__ out) {
    int i = blockIdx.x * 256 + threadIdx.x;   // ull index, NN*OC/2 = 65536 total
    const ull* gp = (const ull*)g_partial;
    ull v = gp[i];
#pragma unroll
    for (int mc = 1; mc < MSPLIT; mc++)
        v = addf2(v, gp[(size_t)mc * (NN * OC / 2) + i]);
    ((ull*)out)[i] = v;
}

extern "C" void kernel_launch(void* const* d_in, const int* in_sizes, int n_in,
                              void* d_out, int out_size) {
    const float* x    = (const float*)d_in[0];
    const float* w    = (const float*)d_in[1];
    const float* b    = (const float*)d_in[2];
    const float* adj  = (const float*)d_in[3];
    const float* attp = (const float*)d_in[4];
    float* out = (float*)d_out;

    support_kernel<<<NN / 128, 128>>>(x, w, b);

    cudaFuncSetAttribute(gcn_main, cudaFuncAttributeMaxDynamicSharedMemorySize,
                         SMEM_BYTES);
    gcn_main<<<dim3(NN / 64, MSPLIT), 128, SMEM_BYTES>>>(adj, attp);

    reduce_kernel<<<(NN * OC / 2) / 256, 256>>>(out);
}

// round 4
// speedup vs baseline: 1.6175x; 1.2413x over previous
#include <cuda_runtime.h>
#include <cstdint>
#include <cstddef>

#define NN   8192
#define IC   128
#define OC   16
#define KH   3
#define MT   1024             // m-tile rows cached in smem
#define PLANE 1092            // ull per d-pair plane; 1092 % 16 == 4 (store-conflict-free)
#define SMEM_BYTES (8 * PLANE * 8)   // 69888 B per CTA
#define MSPLIT 2              // m-dimension split across CTAs

typedef unsigned long long ull;

__device__ __align__(16) float g_support[NN * OC];            // 512 KB
__device__ __align__(16) float g_partial[MSPLIT * NN * OC];   // 1 MB

// ---------- packed f32x2 helpers ----------
__device__ __forceinline__ ull pack_dup(float v) {
    ull r; asm("mov.b64 %0, {%1, %1};" : "=l"(r) : "f"(v)); return r;
}
__device__ __forceinline__ ull pack2(float x, float y) {
    ull r; asm("mov.b64 %0, {%1, %2};" : "=l"(r) : "f"(x), "f"(y)); return r;
}
__device__ __forceinline__ void ffma2(ull& d, ull a, ull b) {
    asm("fma.rn.f32x2 %0, %1, %2, %0;" : "+l"(d) : "l"(a), "l"(b));
}
__device__ __forceinline__ ull addf2(ull a, ull b) {
    ull r; asm("add.rn.f32x2 %0, %1, %2;" : "=l"(r) : "l"(a), "l"(b)); return r;
}

// ---------- kernel 1: support = x@w + b  (2 threads per row, MLP-8 loads) ----------
__global__ void __launch_bounds__(256)
support_kernel(const float* __restrict__ x, const float* __restrict__ w,
               const float* __restrict__ b) {
    __shared__ ull wsm[IC * OC / 2];     // [c][j]
    __shared__ ull bsm[OC / 2];
    __shared__ ull red[128 * 8];         // odd-thread partials
    int tid = threadIdx.x;
    for (int i = tid; i < IC * OC / 2; i += 256) wsm[i] = ((const ull*)w)[i];
    if (tid < OC / 2) bsm[tid] = ((const ull*)b)[tid];
    __syncthreads();

    int rloc = tid >> 1;                 // 0..127
    int half = tid & 1;                  // c-half
    int m = blockIdx.x * 128 + rloc;

    ull acc[8];
#pragma unroll
    for (int j = 0; j < 8; j++) acc[j] = 0ull;

    const float4* xr = (const float4*)(x + (size_t)m * IC + half * 64);
    float4 xv[16];
#pragma unroll
    for (int c4 = 0; c4 < 16; c4++) xv[c4] = xr[c4];   // 16 independent LDG.128
#pragma unroll
    for (int c4 = 0; c4 < 16; c4++) {
#pragma unroll
        for (int e = 0; e < 4; e++) {
            ull a2 = pack_dup((&xv[c4].x)[e]);
            int c = half * 64 + c4 * 4 + e;
#pragma unroll
            for (int j = 0; j < 8; j++) ffma2(acc[j], a2, wsm[c * 8 + j]);
        }
    }
    if (half) {
#pragma unroll
        for (int j = 0; j < 8; j++) red[rloc * 8 + j] = acc[j];
    }
    __syncthreads();
    if (!half) {
        ull* o = (ull*)g_support;
#pragma unroll
        for (int j = 0; j < 8; j++) {
            ull v = addf2(acc[j], red[rloc * 8 + j]);
            v = addf2(v, bsm[j]);
            o[(size_t)m * 8 + j] = v;
        }
    }
}

// ---------- kernel 2 ----------
// 256 threads: s = tid&15 (16 m-slots -> full 128B LDS wavefronts),
// r2 = tid>>4 (0..15). Each thread owns 4 rows: rb*64 + r2 + 16*r.
// Planar smem, injective pad idx = m + (m>>4), plane stride 1092 (=4 mod 16).
__global__ void __launch_bounds__(256, 2)
gcn_main(const float* __restrict__ adj, const float* __restrict__ attp) {
    extern __shared__ ull sp[];
    int tid = threadIdx.x;
    int s   = tid & 15;
    int r2  = tid >> 4;                  // 0..15
    int rb  = blockIdx.x;                // row block (64 rows)
    int mc  = blockIdx.y;                // m chunk (4096 m)

    float p0 = attp[0], p1 = attp[1], p2 = attp[2];
    float mx = fmaxf(p0, fmaxf(p1, p2));
    float e0 = expf(p0 - mx), e1 = expf(p1 - mx), e2 = expf(p2 - mx);
    float inv = 1.0f / (e0 + e1 + e2);
    float att[KH] = {e0 * inv, e1 * inv, e2 * inv};

    int row0 = rb * 64 + r2;             // rows: row0 + 16*r

    ull acc[32];
#pragma unroll
    for (int j = 0; j < 32; j++) acc[j] = 0ull;

    const float4* supp4 = (const float4*)g_support;

    for (int k = 0; k < KH; k++) {
        const float4* pr[4];
#pragma unroll
        for (int r = 0; r < 4; r++)
            pr[r] = (const float4*)(adj + ((size_t)k * NN + row0 + 16 * r) * NN);
        float ak = att[k];

        for (int t = 0; t < 4; t++) {
            int tile0 = (mc * 4 + t) * MT;
            __syncthreads();
            // cooperative tile load (att_k folded in); 16 iters/thread
            for (int idx = tid; idx < MT * (OC / 4); idx += 256) {
                int m  = idx >> 2;
                int dq = idx & 3;
                float4 v = supp4[(size_t)(tile0 + m) * (OC / 4) + dq];
                int base = m + (m >> 4);
                int j0 = dq * 2;
                sp[(size_t)j0 * PLANE + base]       = pack2(v.x * ak, v.y * ak);
                sp[(size_t)(j0 + 1) * PLANE + base] = pack2(v.z * ak, v.w * ak);
            }
            __syncthreads();

            const float4* p[4];
#pragma unroll
            for (int r = 0; r < 4; r++) p[r] = pr[r] + (tile0 >> 2);

            // dist-1 prefetch over 16 float4s per row of this tile
            float4 c[4], n[4];
#pragma unroll
            for (int r = 0; r < 4; r++) c[r] = p[r][s];

#pragma unroll 1
            for (int i = 0; i < 16; i++) {
                int fn = s + 16 * (i + 1); if (fn > 255) fn = s;
#pragma unroll
                for (int r = 0; r < 4; r++) n[r] = p[r][fn];

                int fl = s + 16 * i;
                int base = 4 * fl + (fl >> 2);   // = m + (m>>4) for m=4*fl (same 16-block)
#pragma unroll
                for (int jp = 0; jp < 4; jp++) {
                    ull a0 = pack_dup((&c[0].x)[jp]);
                    ull a1 = pack_dup((&c[1].x)[jp]);
                    ull a2 = pack_dup((&c[2].x)[jp]);
                    ull a3 = pack_dup((&c[3].x)[jp]);
                    const ull* q = sp + base + jp;
#pragma unroll
                    for (int j = 0; j < 8; j++) {
                        ull sv = q[(size_t)j * PLANE];
                        ffma2(acc[j],      a0, sv);
                        ffma2(acc[8 + j],  a1, sv);
                        ffma2(acc[16 + j], a2, sv);
                        ffma2(acc[24 + j], a3, sv);
                    }
                }
#pragma unroll
                for (int r = 0; r < 4; r++) c[r] = n[r];
            }
        }
    }

    // reduce the 16 m-slots: lanes 0..15 / 16..31 are independent r2 groups;
    // xor masks < 16 stay within each group.
#pragma unroll
    for (int j = 0; j < 32; j++) {
        acc[j] = addf2(acc[j], __shfl_xor_sync(0xffffffffu, acc[j], 8));
        acc[j] = addf2(acc[j], __shfl_xor_sync(0xffffffffu, acc[j], 4));
        acc[j] = addf2(acc[j], __shfl_xor_sync(0xffffffffu, acc[j], 2));
        acc[j] = addf2(acc[j], __shfl_xor_sync(0xffffffffu, acc[j], 1));
    }
    if (s == 0) {
        ull* gp = (ull*)g_partial;
#pragma unroll
        for (int r = 0; r < 4; r++) {
            size_t row = row0 + 16 * r;
#pragma unroll
            for (int j = 0; j < 8; j++)
                gp[((size_t)mc * NN + row) * 8 + j] = acc[r * 8 + j];
        }
    }
}

// ---------- kernel 3: out = sum over MSPLIT partials ----------
__global__ void __launch_bounds__(256)
reduce_kernel(float* __restrict__ out) {
    int i = blockIdx.x * 256 + threadIdx.x;   // NN*OC/2 = 65536 ull
    const ull* gp = (const ull*)g_partial;
    ull v = gp[i];
#pragma unroll
    for (int mc = 1; mc < MSPLIT; mc++)
        v = addf2(v, gp[(size_t)mc * (NN * OC / 2) + i]);
    ((ull*)out)[i] = v;
}

extern "C" void kernel_launch(void* const* d_in, const int* in_sizes, int n_in,
                              void* d_out, int out_size) {
    const float* x    = (const float*)d_in[0];
    const float* w    = (const float*)d_in[1];
    const float* b    = (const float*)d_in[2];
    const float* adj  = (const float*)d_in[3];
    const float* attp = (const float*)d_in[4];
    float* out = (float*)d_out;

    support_kernel<<<NN / 128, 256>>>(x, w, b);

    cudaFuncSetAttribute(gcn_main, cudaFuncAttributeMaxDynamicSharedMemorySize,
                         SMEM_BYTES);
    gcn_main<<<dim3(NN / 64, MSPLIT), 256, SMEM_BYTES>>>(adj, attp);

    reduce_kernel<<<(NN * OC / 2) / 256, 256>>>(out);
}

// round 6
// speedup vs baseline: 1.8293x; 1.1310x over previous
#include <cuda_runtime.h>
#include <cuda_bf16.h>
#include <cstdint>
#include <cstddef>

#define NN 8192
#define IC 128
#define OC 16
#define KH 3
#define CH 64                           // k-extent per chunk
#define MSPLIT 4
#define CPH (NN / MSPLIT / CH)          // 32 chunks per hop per CTA
#define A_BYTES (128 * CH * 2)          // 16 KB per (hi|lo) tile
#define DYN_SMEM (2 * A_BYTES + 1024)   // 33792

typedef unsigned long long ull;

__device__ __align__(16) float g_support[NN * OC];             // 512 KB
// B fragments, per-lane layout: [hop][g16(512)][nt(2)][lane(32)] = uint4{bh0,bh1,bl0,bl1}
__device__ __align__(16) uint4 g_Bfrag[KH * 512 * 2 * 32];     // 1.5 MB
__device__ __align__(16) float g_partial[MSPLIT * NN * OC];    // 2 MB

// ---------- helpers ----------
__device__ __forceinline__ ull pack_dup(float v) {
    ull r; asm("mov.b64 %0, {%1, %1};" : "=l"(r) : "f"(v)); return r;
}
__device__ __forceinline__ void ffma2(ull& d, ull a, ull b) {
    asm("fma.rn.f32x2 %0, %1, %2, %0;" : "+l"(d) : "l"(a), "l"(b));
}
__device__ __forceinline__ ull addf2(ull a, ull b) {
    ull r; asm("add.rn.f32x2 %0, %1, %2;" : "=l"(r) : "l"(a), "l"(b)); return r;
}
__device__ __forceinline__ uint32_t smem_u32(const void* p) {
    uint32_t a;
    asm("{ .reg .u64 t; cvta.to.shared.u64 t, %1; cvt.u32.u64 %0, t; }" : "=r"(a) : "l"(p));
    return a;
}
__device__ __forceinline__ uint32_t sw128(uint32_t off) {
    return off ^ ((off >> 3) & 0x70);
}
// hi = fp32 truncated to bf16 (top 16 bits); lo = rn(v - hi)
__device__ __forceinline__ void split2(float v0, float v1, uint32_t& hi, uint32_t& lo) {
    uint32_t u0 = __float_as_uint(v0), u1 = __float_as_uint(v1);
    asm("prmt.b32 %0, %1, %2, 0x7632;" : "=r"(hi) : "r"(u0), "r"(u1));
    float l0 = v0 - __uint_as_float(u0 & 0xFFFF0000u);
    float l1 = v1 - __uint_as_float(u1 & 0xFFFF0000u);
    asm("cvt.rn.bf16x2.f32 %0, %1, %2;" : "=r"(lo) : "f"(l1), "f"(l0));
}
__device__ __forceinline__ void mma16816(float* d, const uint32_t* a,
                                         uint32_t b0, uint32_t b1) {
    asm volatile(
        "mma.sync.aligned.m16n8k16.row.col.f32.bf16.bf16.f32 "
        "{%0,%1,%2,%3}, {%4,%5,%6,%7}, {%8,%9}, {%0,%1,%2,%3};"
        : "+f"(d[0]), "+f"(d[1]), "+f"(d[2]), "+f"(d[3])
        : "r"(a[0]), "r"(a[1]), "r"(a[2]), "r"(a[3]), "r"(b0), "r"(b1));
}
__device__ __forceinline__ void ldsm4(uint32_t* r, uint32_t addr) {
    asm volatile("ldmatrix.sync.aligned.m8n8.x4.shared.b16 {%0,%1,%2,%3}, [%4];"
                 : "=r"(r[0]), "=r"(r[1]), "=r"(r[2]), "=r"(r[3]) : "r"(addr));
}

// ---------- kernel 1: support = x@w + b (4 threads/row) ----------
__global__ void __launch_bounds__(256)
support_kernel(const float* __restrict__ x, const float* __restrict__ w,
               const float* __restrict__ b) {
    __shared__ ull wsm[IC * OC / 2];
    __shared__ ull bsm[OC / 2];
    int tid = threadIdx.x;
    for (int i = tid; i < IC * OC / 2; i += 256) wsm[i] = ((const ull*)w)[i];
    if (tid < OC / 2) bsm[tid] = ((const ull*)b)[tid];
    __syncthreads();

    int rloc = tid >> 2, q = tid & 3;
    int m = blockIdx.x * 64 + rloc;
    ull acc[8];
#pragma unroll
    for (int j = 0; j < 8; j++) acc[j] = 0ull;

    const float4* xr = (const float4*)(x + (size_t)m * IC + q * 32);
    float4 xv[8];
#pragma unroll
    for (int c4 = 0; c4 < 8; c4++) xv[c4] = xr[c4];
#pragma unroll
    for (int c4 = 0; c4 < 8; c4++)
#pragma unroll
        for (int e = 0; e < 4; e++) {
            ull a2 = pack_dup((&xv[c4].x)[e]);
            int c = q * 32 + c4 * 4 + e;
#pragma unroll
            for (int j = 0; j < 8; j++) ffma2(acc[j], a2, wsm[c * 8 + j]);
        }
#pragma unroll
    for (int j = 0; j < 8; j++) {
        acc[j] = addf2(acc[j], __shfl_xor_sync(0xffffffffu, acc[j], 1));
        acc[j] = addf2(acc[j], __shfl_xor_sync(0xffffffffu, acc[j], 2));
    }
    if (q == 0) {
        ull* o = (ull*)g_support;
#pragma unroll
        for (int j = 0; j < 8; j++) o[(size_t)m * 8 + j] = addf2(acc[j], bsm[j]);
    }
}

// ---------- kernel 2: B fragments (att_k * support), bf16 hi/lo, per-lane layout ----------
__global__ void __launch_bounds__(256)
bsplit_kernel(const float* __restrict__ attp) {
    int idx = blockIdx.x * 256 + threadIdx.x;   // < 3*512*2*32 = 98304
    int lane = idx & 31;
    int nt   = (idx >> 5) & 1;
    int g16  = (idx >> 6) & 511;
    int hop  = idx >> 15;

    float p0 = attp[0], p1 = attp[1], p2 = attp[2];
    float mx = fmaxf(p0, fmaxf(p1, p2));
    float e0 = expf(p0 - mx), e1 = expf(p1 - mx), e2 = expf(p2 - mx);
    float inv = 1.0f / (e0 + e1 + e2);
    float a = ((hop == 0) ? e0 : (hop == 1) ? e1 : e2) * inv;

    int k0 = g16 * 16 + (lane & 3) * 2;
    int d  = nt * 8 + (lane >> 2);
    float v00 = a * g_support[(size_t)(k0 + 0) * OC + d];
    float v01 = a * g_support[(size_t)(k0 + 1) * OC + d];
    float v10 = a * g_support[(size_t)(k0 + 8) * OC + d];
    float v11 = a * g_support[(size_t)(k0 + 9) * OC + d];
    uint32_t bh0, bl0, bh1, bl1;
    split2(v00, v01, bh0, bl0);
    split2(v10, v11, bh1, bl1);
    g_Bfrag[idx] = make_uint4(bh0, bh1, bl0, bl1);
}

// ---------- kernel 3: main GEMM via ldmatrix + mma.sync (bf16 hi/lo, 3 terms) ----------
__global__ void __launch_bounds__(256, 2)
gcn_main(const float* __restrict__ adj) {
    extern __shared__ char dsm[];
    int tid = threadIdx.x, lane = tid & 31, w = tid >> 5;
    int rb = blockIdx.x;                  // 64 row blocks of 128
    int ms = blockIdx.y;                  // MSPLIT chunk of k-dim

    uint32_t sb = (smem_u32(dsm) + 1023u) & ~1023u;
    uint32_t Ah = sb, Al = sb + A_BYTES;

    // ldmatrix per-lane address components (A tile: 128 rows x 128B, SW128)
    int lr = w * 16 + (lane & 15);        // row within 128-row block
    uint32_t rowterm = (uint32_t)lr * 128u;
    uint32_t xorv = (uint32_t)(lr & 7) << 4;
    uint32_t lh16 = (uint32_t)(lane >> 4) * 16u;

    float acc[8];
#pragma unroll
    for (int j = 0; j < 8; j++) acc[j] = 0.0f;

    // conversion thread mapping: f = tid + it*256 -> row=f>>4 (same mq per thread)
    int crow = tid >> 4, cmq = tid & 15;

    for (int hop = 0; hop < KH; hop++) {
        const float4* src =
            (const float4*)(adj + ((size_t)hop * NN + (size_t)rb * 128) * NN);
#pragma unroll 1
        for (int t = 0; t < CPH; t++) {
            int m0 = ms * (NN / MSPLIT) + t * CH;
            // ---- stage loads (before sync -> overlaps other warps' MMA) ----
            float4 v[8];
            const float4* s0 = src + (m0 >> 2) + (size_t)crow * (NN / 4) + cmq;
#pragma unroll
            for (int it = 0; it < 8; it++)
                v[it] = s0[(size_t)it * 16 * (NN / 4)];

            __syncthreads();   // all warps done reading smem of previous chunk
            // ---- convert fp32 -> bf16 hi/lo, STS swizzled ----
#pragma unroll
            for (int it = 0; it < 8; it++) {
                int row = crow + it * 16;
                uint32_t h01, l01, h23, l23;
                split2(v[it].x, v[it].y, h01, l01);
                split2(v[it].z, v[it].w, h23, l23);
                uint32_t sw = sw128((uint32_t)(row * 128 + cmq * 8));
                asm volatile("st.shared.v2.b32 [%0], {%1, %2};"
                             :: "r"(Ah + sw), "r"(h01), "r"(h23) : "memory");
                asm volatile("st.shared.v2.b32 [%0], {%1, %2};"
                             :: "r"(Al + sw), "r"(l01), "r"(l23) : "memory");
            }
            __syncthreads();   // tile visible

            // ---- 4 k16 slices: ldmatrix + 6 mma each ----
            int bbase = ((hop * 512 + (ms * (NN / MSPLIT) >> 4) + t * 4) * 2) * 32 + lane;
#pragma unroll
            for (int kk = 0; kk < 4; kk++) {
                uint32_t off = ((uint32_t)kk * 32u + lh16) ^ xorv;
                uint32_t ah[4], al[4];
                ldsm4(ah, Ah + rowterm + off);
                ldsm4(al, Al + rowterm + off);
                uint4 B0 = g_Bfrag[bbase + (kk * 2 + 0) * 32];
                uint4 B1 = g_Bfrag[bbase + (kk * 2 + 1) * 32];
                // n-tile 0: AhBh + AlBh + AhBl
                mma16816(acc,     ah, B0.x, B0.y);
                mma16816(acc,     al, B0.x, B0.y);
                mma16816(acc,     ah, B0.z, B0.w);
                // n-tile 1
                mma16816(acc + 4, ah, B1.x, B1.y);
                mma16816(acc + 4, al, B1.x, B1.y);
                mma16816(acc + 4, ah, B1.z, B1.w);
            }
        }
    }

    // ---- epilogue: D fragment -> g_partial ----
    int orow = rb * 128 + w * 16 + (lane >> 2);
    int ocol = (lane & 3) * 2;
    float* gp = g_partial + ((size_t)ms * NN + orow) * OC;
#pragma unroll
    for (int nt = 0; nt < 2; nt++) {
        *(float2*)(gp + nt * 8 + ocol) =
            make_float2(acc[nt * 4 + 0], acc[nt * 4 + 1]);
        *(float2*)(gp + (size_t)8 * OC + nt * 8 + ocol) =
            make_float2(acc[nt * 4 + 2], acc[nt * 4 + 3]);
    }
}

// ---------- kernel 4: out = sum over MSPLIT partials ----------
__global__ void __launch_bounds__(256)
reduce_kernel(float* __restrict__ out) {
    int i = blockIdx.x * 256 + threadIdx.x;   // float4 index, NN*OC/4 = 32768
    const float4* gp = (const float4*)g_partial;
    float4 a = gp[i];
#pragma unroll
    for (int mc = 1; mc < MSPLIT; mc++) {
        float4 v = gp[(size_t)mc * (NN * OC / 4) + i];
        a.x += v.x; a.y += v.y; a.z += v.z; a.w += v.w;
    }
    ((float4*)out)[i] = a;
}

extern "C" void kernel_launch(void* const* d_in, const int* in_sizes, int n_in,
                              void* d_out, int out_size) {
    const float* x    = (const float*)d_in[0];
    const float* w    = (const float*)d_in[1];
    const float* b    = (const float*)d_in[2];
    const float* adj  = (const float*)d_in[3];
    const float* attp = (const float*)d_in[4];
    float* out = (float*)d_out;

    support_kernel<<<NN / 64, 256>>>(x, w, b);
    bsplit_kernel<<<(KH * 512 * 2 * 32) / 256, 256>>>(attp);

    cudaFuncSetAttribute(gcn_main, cudaFuncAttributeMaxDynamicSharedMemorySize,
                         DYN_SMEM);
    gcn_main<<<dim3(NN / 128, MSPLIT), 256, DYN_SMEM>>>(adj);

    reduce_kernel<<<(NN * OC / 4) / 256, 256>>>(out);
}

// round 7
// speedup vs baseline: 2.5349x; 1.3857x over previous
#include <cuda_runtime.h>
#include <cuda_bf16.h>
#include <cstdint>
#include <cstddef>

#define NN 8192
#define IC 128
#define OC 16
#define KH 3
#define CH 64                           // k-extent per chunk
#define MSPLIT 4
#define CPH (NN / MSPLIT / CH)          // 32 chunks per hop per CTA
#define TOTC (KH * CPH)                 // 96
#define A_BYTES (128 * CH * 2)          // 16 KB per (hi|lo) tile
#define BUF_BYTES (2 * A_BYTES)         // 32 KB per stage
#define DYN_SMEM (2 * BUF_BYTES + 1024) // 66560

typedef unsigned long long ull;

__device__ __align__(16) float g_support[NN * OC];             // 512 KB
// B fragments, per-lane layout: [hop][g16(512)][nt(2)][lane(32)] = uint4{bh0,bh1,bl0,bl1}
__device__ __align__(16) uint4 g_Bfrag[KH * 512 * 2 * 32];     // 1.5 MB
__device__ __align__(16) float g_partial[MSPLIT * NN * OC];    // 2 MB

// ---------- helpers ----------
__device__ __forceinline__ ull pack_dup(float v) {
    ull r; asm("mov.b64 %0, {%1, %1};" : "=l"(r) : "f"(v)); return r;
}
__device__ __forceinline__ void ffma2(ull& d, ull a, ull b) {
    asm("fma.rn.f32x2 %0, %1, %2, %0;" : "+l"(d) : "l"(a), "l"(b));
}
__device__ __forceinline__ ull addf2(ull a, ull b) {
    ull r; asm("add.rn.f32x2 %0, %1, %2;" : "=l"(r) : "l"(a), "l"(b)); return r;
}
__device__ __forceinline__ uint32_t smem_u32(const void* p) {
    uint32_t a;
    asm("{ .reg .u64 t; cvta.to.shared.u64 t, %1; cvt.u32.u64 %0, t; }" : "=r"(a) : "l"(p));
    return a;
}
__device__ __forceinline__ uint32_t sw128(uint32_t off) {
    return off ^ ((off >> 3) & 0x70);
}
// hi = fp32 truncated to bf16 (top 16 bits); lo = rn(v - hi)
__device__ __forceinline__ void split2(float v0, float v1, uint32_t& hi, uint32_t& lo) {
    uint32_t u0 = __float_as_uint(v0), u1 = __float_as_uint(v1);
    asm("prmt.b32 %0, %1, %2, 0x7632;" : "=r"(hi) : "r"(u0), "r"(u1));
    float l0 = v0 - __uint_as_float(u0 & 0xFFFF0000u);
    float l1 = v1 - __uint_as_float(u1 & 0xFFFF0000u);
    asm("cvt.rn.bf16x2.f32 %0, %1, %2;" : "=r"(lo) : "f"(l1), "f"(l0));
}
__device__ __forceinline__ void mma16816(float* d, const uint32_t* a,
                                         uint32_t b0, uint32_t b1) {
    asm volatile(
        "mma.sync.aligned.m16n8k16.row.col.f32.bf16.bf16.f32 "
        "{%0,%1,%2,%3}, {%4,%5,%6,%7}, {%8,%9}, {%0,%1,%2,%3};"
        : "+f"(d[0]), "+f"(d[1]), "+f"(d[2]), "+f"(d[3])
        : "r"(a[0]), "r"(a[1]), "r"(a[2]), "r"(a[3]), "r"(b0), "r"(b1));
}
__device__ __forceinline__ void ldsm4(uint32_t* r, uint32_t addr) {
    asm volatile("ldmatrix.sync.aligned.m8n8.x4.shared.b16 {%0,%1,%2,%3}, [%4];"
                 : "=r"(r[0]), "=r"(r[1]), "=r"(r[2]), "=r"(r[3]) : "r"(addr));
}

// ---------- kernel 1: support = x@w + b (4 threads/row) ----------
__global__ void __launch_bounds__(256)
support_kernel(const float* __restrict__ x, const float* __restrict__ w,
               const float* __restrict__ b) {
    __shared__ ull wsm[IC * OC / 2];
    __shared__ ull bsm[OC / 2];
    int tid = threadIdx.x;
    for (int i = tid; i < IC * OC / 2; i += 256) wsm[i] = ((const ull*)w)[i];
    if (tid < OC / 2) bsm[tid] = ((const ull*)b)[tid];
    __syncthreads();

    int rloc = tid >> 2, q = tid & 3;
    int m = blockIdx.x * 64 + rloc;
    ull acc[8];
#pragma unroll
    for (int j = 0; j < 8; j++) acc[j] = 0ull;

    const float4* xr = (const float4*)(x + (size_t)m * IC + q * 32);
    float4 xv[8];
#pragma unroll
    for (int c4 = 0; c4 < 8; c4++) xv[c4] = xr[c4];
#pragma unroll
    for (int c4 = 0; c4 < 8; c4++)
#pragma unroll
        for (int e = 0; e < 4; e++) {
            ull a2 = pack_dup((&xv[c4].x)[e]);
            int c = q * 32 + c4 * 4 + e;
#pragma unroll
            for (int j = 0; j < 8; j++) ffma2(acc[j], a2, wsm[c * 8 + j]);
        }
#pragma unroll
    for (int j = 0; j < 8; j++) {
        acc[j] = addf2(acc[j], __shfl_xor_sync(0xffffffffu, acc[j], 1));
        acc[j] = addf2(acc[j], __shfl_xor_sync(0xffffffffu, acc[j], 2));
    }
    if (q == 0) {
        ull* o = (ull*)g_support;
#pragma unroll
        for (int j = 0; j < 8; j++) o[(size_t)m * 8 + j] = addf2(acc[j], bsm[j]);
    }
}

// ---------- kernel 2: B fragments (att_k * support), bf16 hi/lo, per-lane layout ----------
__global__ void __launch_bounds__(256)
bsplit_kernel(const float* __restrict__ attp) {
    int idx = blockIdx.x * 256 + threadIdx.x;   // < 3*512*2*32 = 98304
    int lane = idx & 31;
    int nt   = (idx >> 5) & 1;
    int g16  = (idx >> 6) & 511;
    int hop  = idx >> 15;

    float p0 = attp[0], p1 = attp[1], p2 = attp[2];
    float mx = fmaxf(p0, fmaxf(p1, p2));
    float e0 = expf(p0 - mx), e1 = expf(p1 - mx), e2 = expf(p2 - mx);
    float inv = 1.0f / (e0 + e1 + e2);
    float a = ((hop == 0) ? e0 : (hop == 1) ? e1 : e2) * inv;

    int k0 = g16 * 16 + (lane & 3) * 2;
    int d  = nt * 8 + (lane >> 2);
    float v00 = a * g_support[(size_t)(k0 + 0) * OC + d];
    float v01 = a * g_support[(size_t)(k0 + 1) * OC + d];
    float v10 = a * g_support[(size_t)(k0 + 8) * OC + d];
    float v11 = a * g_support[(size_t)(k0 + 9) * OC + d];
    uint32_t bh0, bl0, bh1, bl1;
    split2(v00, v01, bh0, bl0);
    split2(v10, v11, bh1, bl1);
    g_Bfrag[idx] = make_uint4(bh0, bh1, bl0, bl1);
}

// ---------- kernel 3: main GEMM, double-buffered, 1 barrier/chunk ----------
__global__ void __launch_bounds__(256, 2)
gcn_main(const float* __restrict__ adj) {
    extern __shared__ char dsm[];
    int tid = threadIdx.x, lane = tid & 31, w = tid >> 5;
    int rb = blockIdx.x;                  // 64 row blocks of 128
    int ms = blockIdx.y;                  // MSPLIT chunk of k-dim

    uint32_t sb = (smem_u32(dsm) + 1023u) & ~1023u;

    // ldmatrix per-lane address components (A tile: 128 rows x 128B, SW128)
    int lr = w * 16 + (lane & 15);
    uint32_t rowterm = (uint32_t)lr * 128u;
    uint32_t xorv = (uint32_t)(lr & 7) << 4;
    uint32_t lh16 = (uint32_t)(lane >> 4) * 16u;

    float acc[8];
#pragma unroll
    for (int j = 0; j < 8; j++) acc[j] = 0.0f;

    // conversion thread mapping
    int crow = tid >> 4, cmq = tid & 15;
    const float4* adjf4 = (const float4*)adj;
    size_t rowoff = (size_t)(rb * 128 + crow) * (NN / 4) + (size_t)ms * 512 + cmq;

    float4 v[8];
    // prologue: load chunk 0 (hop 0, t 0)
    {
        const float4* p = adjf4 + rowoff;
#pragma unroll
        for (int it = 0; it < 8; it++) v[it] = p[(size_t)it * 16 * (NN / 4)];
    }

#pragma unroll 1
    for (int c = 0; c < TOTC; c++) {
        int hop = c >> 5, t = c & 31;     // CPH == 32
        uint32_t Ah = sb + (uint32_t)(c & 1) * BUF_BYTES;
        uint32_t Al = Ah + A_BYTES;

        // ---- convert staged chunk c into buf[c&1] ----
#pragma unroll
        for (int it = 0; it < 8; it++) {
            int row = crow + it * 16;
            uint32_t h01, l01, h23, l23;
            split2(v[it].x, v[it].y, h01, l01);
            split2(v[it].z, v[it].w, h23, l23);
            uint32_t sw = sw128((uint32_t)(row * 128 + cmq * 8));
            asm volatile("st.shared.v2.b32 [%0], {%1, %2};"
                         :: "r"(Ah + sw), "r"(h01), "r"(h23) : "memory");
            asm volatile("st.shared.v2.b32 [%0], {%1, %2};"
                         :: "r"(Al + sw), "r"(l01), "r"(l23) : "memory");
        }

        // ---- prefetch chunk c+1 (stays in flight through the MMA phase) ----
        if (c + 1 < TOTC) {
            int c1 = c + 1;
            int hop1 = c1 >> 5, t1 = c1 & 31;
            const float4* p = adjf4 + (size_t)hop1 * NN * (NN / 4) + rowoff + t1 * 16;
#pragma unroll
            for (int it = 0; it < 8; it++) v[it] = p[(size_t)it * 16 * (NN / 4)];
        }

        __syncthreads();   // buf[c&1] ready; prior reads of buf[(c+1)&1] all retired

        // ---- 4 k16 slices: ldmatrix + 6 mma each ----
        int bbase = ((hop * 512 + ms * 128 + t * 4) * 2) * 32 + lane;
#pragma unroll
        for (int kk = 0; kk < 4; kk++) {
            uint32_t off = ((uint32_t)kk * 32u + lh16) ^ xorv;
            uint32_t ah[4], al[4];
            ldsm4(ah, Ah + rowterm + off);
            ldsm4(al, Al + rowterm + off);
            uint4 B0 = __ldg(&g_Bfrag[bbase + (kk * 2 + 0) * 32]);
            uint4 B1 = __ldg(&g_Bfrag[bbase + (kk * 2 + 1) * 32]);
            mma16816(acc,     ah, B0.x, B0.y);
            mma16816(acc,     al, B0.x, B0.y);
            mma16816(acc,     ah, B0.z, B0.w);
            mma16816(acc + 4, ah, B1.x, B1.y);
            mma16816(acc + 4, al, B1.x, B1.y);
            mma16816(acc + 4, ah, B1.z, B1.w);
        }
    }

    // ---- epilogue: D fragment -> g_partial ----
    int orow = rb * 128 + w * 16 + (lane >> 2);
    int ocol = (lane & 3) * 2;
    float* gp = g_partial + ((size_t)ms * NN + orow) * OC;
#pragma unroll
    for (int nt = 0; nt < 2; nt++) {
        *(float2*)(gp + nt * 8 + ocol) =
            make_float2(acc[nt * 4 + 0], acc[nt * 4 + 1]);
        *(float2*)(gp + (size_t)8 * OC + nt * 8 + ocol) =
            make_float2(acc[nt * 4 + 2], acc[nt * 4 + 3]);
    }
}

// ---------- kernel 4: out = sum over MSPLIT partials ----------
__global__ void __launch_bounds__(256)
reduce_kernel(float* __restrict__ out) {
    int i = blockIdx.x * 256 + threadIdx.x;   // float4 index, NN*OC/4 = 32768
    const float4* gp = (const float4*)g_partial;
    float4 a = gp[i];
#pragma unroll
    for (int mc = 1; mc < MSPLIT; mc++) {
        float4 v = gp[(size_t)mc * (NN * OC / 4) + i];
        a.x += v.x; a.y += v.y; a.z += v.z; a.w += v.w;
    }
    ((float4*)out)[i] = a;
}

extern "C" void kernel_launch(void* const* d_in, const int* in_sizes, int n_in,
                              void* d_out, int out_size) {
    const float* x    = (const float*)d_in[0];
    const float* w    = (const float*)d_in[1];
    const float* b    = (const float*)d_in[2];
    const float* adj  = (const float*)d_in[3];
    const float* attp = (const float*)d_in[4];
    float* out = (float*)d_out;

    support_kernel<<<NN / 64, 256>>>(x, w, b);
    bsplit_kernel<<<(KH * 512 * 2 * 32) / 256, 256>>>(attp);

    cudaFuncSetAttribute(gcn_main, cudaFuncAttributeMaxDynamicSharedMemorySize,
                         DYN_SMEM);
    gcn_main<<<dim3(NN / 128, MSPLIT), 256, DYN_SMEM>>>(adj);

    reduce_kernel<<<(NN * OC / 4) / 256, 256>>>(out);
}

// round 8
// speedup vs baseline: 2.5441x; 1.0037x over previous
#include <cuda_runtime.h>
#include <cuda_bf16.h>
#include <cstdint>
#include <cstddef>

#define NN 8192
#define IC 128
#define OC 16
#define KH 3
#define CH 64                           // k-extent per chunk
#define MSPLIT 4
#define CPH (NN / MSPLIT / CH)          // 32 chunks per hop per CTA
#define TOTC (KH * CPH)                 // 96
#define A_BYTES (128 * CH * 2)          // 16 KB per (hi|lo) tile
#define BUF_BYTES (2 * A_BYTES)         // 32 KB per stage
#define DYN_SMEM (2 * BUF_BYTES + 1024) // 66560

typedef unsigned long long ull;

// B fragments, per-lane layout: idx = hop<<15 | g16<<6 | nt<<5 | lane -> uint4{bh0,bh1,bl0,bl1}
__device__ __align__(16) uint4 g_Bfrag[KH * 512 * 2 * 32];     // 1.5 MB
__device__ __align__(16) float g_partial[MSPLIT * NN * OC];    // 2 MB
__device__ int g_cnt[NN / 128];                                // zero-init; self-resetting

// ---------- helpers ----------
__device__ __forceinline__ ull pack_dup(float v) {
    ull r; asm("mov.b64 %0, {%1, %1};" : "=l"(r) : "f"(v)); return r;
}
__device__ __forceinline__ void ffma2(ull& d, ull a, ull b) {
    asm("fma.rn.f32x2 %0, %1, %2, %0;" : "+l"(d) : "l"(a), "l"(b));
}
__device__ __forceinline__ ull addf2(ull a, ull b) {
    ull r; asm("add.rn.f32x2 %0, %1, %2;" : "=l"(r) : "l"(a), "l"(b)); return r;
}
__device__ __forceinline__ uint32_t smem_u32(const void* p) {
    uint32_t a;
    asm("{ .reg .u64 t; cvta.to.shared.u64 t, %1; cvt.u32.u64 %0, t; }" : "=r"(a) : "l"(p));
    return a;
}
__device__ __forceinline__ uint32_t sw128(uint32_t off) {
    return off ^ ((off >> 3) & 0x70);
}
// hi = fp32 truncated to bf16 (top 16 bits); lo = rn(v - hi)
__device__ __forceinline__ void split2(float v0, float v1, uint32_t& hi, uint32_t& lo) {
    uint32_t u0 = __float_as_uint(v0), u1 = __float_as_uint(v1);
    asm("prmt.b32 %0, %1, %2, 0x7632;" : "=r"(hi) : "r"(u0), "r"(u1));
    float l0 = v0 - __uint_as_float(u0 & 0xFFFF0000u);
    float l1 = v1 - __uint_as_float(u1 & 0xFFFF0000u);
    asm("cvt.rn.bf16x2.f32 %0, %1, %2;" : "=r"(lo) : "f"(l1), "f"(l0));
}
__device__ __forceinline__ void mma16816(float* d, const uint32_t* a,
                                         uint32_t b0, uint32_t b1) {
    asm volatile(
        "mma.sync.aligned.m16n8k16.row.col.f32.bf16.bf16.f32 "
        "{%0,%1,%2,%3}, {%4,%5,%6,%7}, {%8,%9}, {%0,%1,%2,%3};"
        : "+f"(d[0]), "+f"(d[1]), "+f"(d[2]), "+f"(d[3])
        : "r"(a[0]), "r"(a[1]), "r"(a[2]), "r"(a[3]), "r"(b0), "r"(b1));
}
__device__ __forceinline__ void ldsm4(uint32_t* r, uint32_t addr) {
    asm volatile("ldmatrix.sync.aligned.m8n8.x4.shared.b16 {%0,%1,%2,%3}, [%4];"
                 : "=r"(r[0]), "=r"(r[1]), "=r"(r[2]), "=r"(r[3]) : "r"(addr));
}

// ---------- kernel 1: fused prep — support (smem) + B fragments (gmem) ----------
// Block handles 64 support rows = 4 g16 groups; emits fragments for all 3 hops.
__global__ void __launch_bounds__(256)
prep_kernel(const float* __restrict__ x, const float* __restrict__ w,
            const float* __restrict__ b, const float* __restrict__ attp) {
    __shared__ ull   wsm[IC * OC / 2];
    __shared__ ull   bsm[OC / 2];
    __shared__ float s_supp[64 * OC];    // 4 KB
    int tid = threadIdx.x;
    for (int i = tid; i < IC * OC / 2; i += 256) wsm[i] = ((const ull*)w)[i];
    if (tid < OC / 2) bsm[tid] = ((const ull*)b)[tid];
    __syncthreads();

    // --- support for 64 rows, 4 threads/row ---
    int rloc = tid >> 2, q = tid & 3;
    int m = blockIdx.x * 64 + rloc;
    ull acc[8];
#pragma unroll
    for (int j = 0; j < 8; j++) acc[j] = 0ull;

    const float4* xr = (const float4*)(x + (size_t)m * IC + q * 32);
    float4 xv[8];
#pragma unroll
    for (int c4 = 0; c4 < 8; c4++) xv[c4] = xr[c4];
#pragma unroll
    for (int c4 = 0; c4 < 8; c4++)
#pragma unroll
        for (int e = 0; e < 4; e++) {
            ull a2 = pack_dup((&xv[c4].x)[e]);
            int c = q * 32 + c4 * 4 + e;
#pragma unroll
            for (int j = 0; j < 8; j++) ffma2(acc[j], a2, wsm[c * 8 + j]);
        }
#pragma unroll
    for (int j = 0; j < 8; j++) {
        acc[j] = addf2(acc[j], __shfl_xor_sync(0xffffffffu, acc[j], 1));
        acc[j] = addf2(acc[j], __shfl_xor_sync(0xffffffffu, acc[j], 2));
    }
    if (q == 0) {
        ull* o = (ull*)(s_supp + rloc * OC);
#pragma unroll
        for (int j = 0; j < 8; j++) o[j] = addf2(acc[j], bsm[j]);
    }
    __syncthreads();

    // --- softmax(att) ---
    float p0 = attp[0], p1 = attp[1], p2 = attp[2];
    float mx = fmaxf(p0, fmaxf(p1, p2));
    float e0 = expf(p0 - mx), e1 = expf(p1 - mx), e2 = expf(p2 - mx);
    float inv = 1.0f / (e0 + e1 + e2);
    float attv[KH] = {e0 * inv, e1 * inv, e2 * inv};

    // --- B fragments: tid = g16loc*64 + nt*32 + lane; 3 hops per thread ---
    int lane = tid & 31, nt = (tid >> 5) & 1, g16loc = tid >> 6;
    int g16 = blockIdx.x * 4 + g16loc;
    int k0l = g16loc * 16 + (lane & 3) * 2;   // local row within 64
    int d   = nt * 8 + (lane >> 2);
    float s00 = s_supp[(k0l + 0) * OC + d];
    float s01 = s_supp[(k0l + 1) * OC + d];
    float s10 = s_supp[(k0l + 8) * OC + d];
    float s11 = s_supp[(k0l + 9) * OC + d];
#pragma unroll
    for (int hop = 0; hop < KH; hop++) {
        float a = attv[hop];
        uint32_t bh0, bl0, bh1, bl1;
        split2(a * s00, a * s01, bh0, bl0);
        split2(a * s10, a * s11, bh1, bl1);
        g_Bfrag[(hop << 15) | (g16 << 6) | (nt << 5) | lane] =
            make_uint4(bh0, bh1, bl0, bl1);
    }
}

// ---------- kernel 2: main GEMM, double-buffered + fused last-CTA reduction ----------
__global__ void __launch_bounds__(256, 2)
gcn_main(const float* __restrict__ adj, float* __restrict__ out) {
    extern __shared__ char dsm[];
    __shared__ int s_last;
    int tid = threadIdx.x, lane = tid & 31, w = tid >> 5;
    int rb = blockIdx.x;                  // 64 row blocks of 128
    int ms = blockIdx.y;                  // MSPLIT chunk of k-dim

    uint32_t sb = (smem_u32(dsm) + 1023u) & ~1023u;

    // ldmatrix per-lane address components (A tile: 128 rows x 128B, SW128)
    int lr = w * 16 + (lane & 15);
    uint32_t rowterm = (uint32_t)lr * 128u;
    uint32_t xorv = (uint32_t)(lr & 7) << 4;
    uint32_t lh16 = (uint32_t)(lane >> 4) * 16u;

    float acc[8];
#pragma unroll
    for (int j = 0; j < 8; j++) acc[j] = 0.0f;

    int crow = tid >> 4, cmq = tid & 15;
    const float4* adjf4 = (const float4*)adj;
    size_t rowoff = (size_t)(rb * 128 + crow) * (NN / 4) + (size_t)ms * 512 + cmq;

    float4 v[8];
    {
        const float4* p = adjf4 + rowoff;
#pragma unroll
        for (int it = 0; it < 8; it++) v[it] = p[(size_t)it * 16 * (NN / 4)];
    }

#pragma unroll 1
    for (int c = 0; c < TOTC; c++) {
        int hop = c >> 5, t = c & 31;
        uint32_t Ah = sb + (uint32_t)(c & 1) * BUF_BYTES;
        uint32_t Al = Ah + A_BYTES;

#pragma unroll
        for (int it = 0; it < 8; it++) {
            int row = crow + it * 16;
            uint32_t h01, l01, h23, l23;
            split2(v[it].x, v[it].y, h01, l01);
            split2(v[it].z, v[it].w, h23, l23);
            uint32_t sw = sw128((uint32_t)(row * 128 + cmq * 8));
            asm volatile("st.shared.v2.b32 [%0], {%1, %2};"
                         :: "r"(Ah + sw), "r"(h01), "r"(h23) : "memory");
            asm volatile("st.shared.v2.b32 [%0], {%1, %2};"
                         :: "r"(Al + sw), "r"(l01), "r"(l23) : "memory");
        }

        if (c + 1 < TOTC) {
            int c1 = c + 1;
            int hop1 = c1 >> 5, t1 = c1 & 31;
            const float4* p = adjf4 + (size_t)hop1 * NN * (NN / 4) + rowoff + t1 * 16;
#pragma unroll
            for (int it = 0; it < 8; it++) v[it] = p[(size_t)it * 16 * (NN / 4)];
        }

        __syncthreads();

        int bbase = ((hop * 512 + ms * 128 + t * 4) * 2) * 32 + lane;
#pragma unroll
        for (int kk = 0; kk < 4; kk++) {
            uint32_t off = ((uint32_t)kk * 32u + lh16) ^ xorv;
            uint32_t ah[4], al[4];
            ldsm4(ah, Ah + rowterm + off);
            ldsm4(al, Al + rowterm + off);
            uint4 B0 = __ldg(&g_Bfrag[bbase + (kk * 2 + 0) * 32]);
            uint4 B1 = __ldg(&g_Bfrag[bbase + (kk * 2 + 1) * 32]);
            mma16816(acc,     ah, B0.x, B0.y);
            mma16816(acc,     al, B0.x, B0.y);
            mma16816(acc,     ah, B0.z, B0.w);
            mma16816(acc + 4, ah, B1.x, B1.y);
            mma16816(acc + 4, al, B1.x, B1.y);
            mma16816(acc + 4, ah, B1.z, B1.w);
        }
    }

    // ---- write this CTA's partial ----
    int orow = rb * 128 + w * 16 + (lane >> 2);
    int ocol = (lane & 3) * 2;
    float* gp = g_partial + ((size_t)ms * NN + orow) * OC;
#pragma unroll
    for (int nt = 0; nt < 2; nt++) {
        *(float2*)(gp + nt * 8 + ocol) =
            make_float2(acc[nt * 4 + 0], acc[nt * 4 + 1]);
        *(float2*)(gp + (size_t)8 * OC + nt * 8 + ocol) =
            make_float2(acc[nt * 4 + 2], acc[nt * 4 + 3]);
    }

    // ---- last-arriving CTA for this rowblock sums the MSPLIT partials ----
    __threadfence();                      // make partials visible
    __syncthreads();                      // all threads' stores precede the arrive
    if (tid == 0) {
        int old = atomicAdd(&g_cnt[rb], 1);
        s_last = (old == MSPLIT - 1);
    }
    __syncthreads();
    if (s_last) {
        __threadfence();                  // acquire: see other CTAs' partials
        // 128 rows x 16 cols = 512 float4; 2 per thread; fixed order -> deterministic
        const float4* base = (const float4*)(g_partial) + (size_t)rb * 128 * (OC / 4);
#pragma unroll
        for (int u = 0; u < 2; u++) {
            int i = tid + u * 256;
            float4 a = base[i];
#pragma unroll
            for (int mc = 1; mc < MSPLIT; mc++) {
                float4 pv = base[(size_t)mc * NN * (OC / 4) + i];
                a.x += pv.x; a.y += pv.y; a.z += pv.z; a.w += pv.w;
            }
            ((float4*)out)[(size_t)rb * 128 * (OC / 4) + i] = a;
        }
        if (tid == 0) g_cnt[rb] = 0;      // self-reset for next graph replay
    }
}

extern "C" void kernel_launch(void* const* d_in, const int* in_sizes, int n_in,
                              void* d_out, int out_size) {
    const float* x    = (const float*)d_in[0];
    const float* w    = (const float*)d_in[1];
    const float* b    = (const float*)d_in[2];
    const float* adj  = (const float*)d_in[3];
    const float* attp = (const float*)d_in[4];
    float* out = (float*)d_out;

    prep_kernel<<<NN / 64, 256>>>(x, w, b, attp);

    cudaFuncSetAttribute(gcn_main, cudaFuncAttributeMaxDynamicSharedMemorySize,
                         DYN_SMEM);
    gcn_main<<<dim3(NN / 128, MSPLIT), 256, DYN_SMEM>>>(adj, out);
}